// round 9
// baseline (speedup 1.0000x reference)
#include <cuda_runtime.h>
#include <cuda_bf16.h>
#include <math.h>

// Problem constants
#define BATCH 2
#define SEQ 2048
#define DMODEL 1024
#define NHEADS 16
#define DK 64
#define MROWS (BATCH * SEQ)   // 4096

// Scratch buffers (device globals: no allocation allowed in kernel_launch)
__device__ float g_Q[MROWS * DMODEL];
__device__ float g_K[MROWS * DMODEL];
__device__ float g_V[MROWS * DMODEL];
__device__ float g_O[MROWS * DMODEL];

// ----------------------------------------------------------------------------
// GEMM (NT): C[m,n] = sum_k A[m,k] * W[n,k]   (A: MxK, W: NxK, both K-contig)
// Tile 64x64, BK=16, 256 threads, 4x4 micro-tile per thread.
// ----------------------------------------------------------------------------
#define BK 16

__global__ void __launch_bounds__(256) gemm_nt(const float* __restrict__ A,
                                               const float* __restrict__ Wm,
                                               float* __restrict__ C,
                                               int M, int N, int K) {
    __shared__ float As[BK][68];   // K-major, pad 68 (float4 aligned)
    __shared__ float Ws[BK][68];

    const int tid = threadIdx.x;
    const int tx = tid & 15;       // 0..15 -> N direction
    const int ty = tid >> 4;       // 0..15 -> M direction
    const int m0 = blockIdx.y * 64;
    const int n0 = blockIdx.x * 64;

    // cooperative load mapping: 256 threads cover 64 rows x 16 K-cols (float4)
    const int lr = tid >> 2;           // 0..63 row within tile
    const int lc = (tid & 3) * 4;      // 0,4,8,12 k-col within tile

    const float* aLoad = A  + (size_t)(m0 + lr) * K + lc;
    const float* wLoad = Wm + (size_t)(n0 + lr) * K + lc;

    float acc[4][4];
#pragma unroll
    for (int i = 0; i < 4; i++)
#pragma unroll
        for (int j = 0; j < 4; j++) acc[i][j] = 0.f;

    for (int k0 = 0; k0 < K; k0 += BK) {
        float4 av = *(const float4*)(aLoad + k0);
        float4 wv = *(const float4*)(wLoad + k0);
        As[lc + 0][lr] = av.x; As[lc + 1][lr] = av.y;
        As[lc + 2][lr] = av.z; As[lc + 3][lr] = av.w;
        Ws[lc + 0][lr] = wv.x; Ws[lc + 1][lr] = wv.y;
        Ws[lc + 2][lr] = wv.z; Ws[lc + 3][lr] = wv.w;
        __syncthreads();

#pragma unroll
        for (int kk = 0; kk < BK; kk++) {
            float4 a = *(const float4*)&As[kk][ty * 4];
            float4 b = *(const float4*)&Ws[kk][tx * 4];
            float ar[4] = {a.x, a.y, a.z, a.w};
            float br[4] = {b.x, b.y, b.z, b.w};
#pragma unroll
            for (int i = 0; i < 4; i++)
#pragma unroll
                for (int j = 0; j < 4; j++)
                    acc[i][j] += ar[i] * br[j];
        }
        __syncthreads();
    }

#pragma unroll
    for (int i = 0; i < 4; i++) {
        float4 o = make_float4(acc[i][0], acc[i][1], acc[i][2], acc[i][3]);
        *(float4*)&C[(size_t)(m0 + ty * 4 + i) * N + n0 + tx * 4] = o;
    }
}

// ----------------------------------------------------------------------------
// RoPE (in-place on Q and K, natural [B,S,D] layout).
// Double-precision angle: pos up to 2047 amplifies freq error, so fp32 powf
// would cost ~1e-3 in sin/cos. Double keeps us <= the reference's own rounding.
// ----------------------------------------------------------------------------
__global__ void rope_kernel(float* __restrict__ Qb, float* __restrict__ Kb,
                            const int* __restrict__ tp) {
    int idx = blockIdx.x * blockDim.x + threadIdx.x;   // over B*S*(D/2)
    if (idx >= BATCH * SEQ * (DMODEL / 2)) return;
    int d2 = idx & (DMODEL / 2 - 1);   // 0..511
    int bs = idx >> 9;                 // 0..4095 (b*S+s)
    int s  = bs & (SEQ - 1);
    int h  = d2 >> 5;                  // head
    int i  = d2 & 31;                  // pair index within head

    double pos  = (double)tp[s];
    // theta^(-(2i)/64) = exp(-(2i/64) * ln(10000))
    double freq = exp(-((double)(2 * i) / 64.0) * 9.210340371976184);
    double ang  = pos * freq;
    float cs = (float)cos(ang);
    float sn = (float)sin(ang);

    size_t base = (size_t)bs * DMODEL + h * DK + 2 * i;
    float q1 = Qb[base], q2 = Qb[base + 1];
    Qb[base]     = q1 * cs - q2 * sn;
    Qb[base + 1] = q1 * sn + q2 * cs;
    float k1 = Kb[base], k2 = Kb[base + 1];
    Kb[base]     = k1 * cs - k2 * sn;
    Kb[base + 1] = k1 * sn + k2 * cs;
}

// ----------------------------------------------------------------------------
// Causal flash attention. One block = one (b, h, 64-row q tile).
// 64 threads: thread t owns query row t. Q row + O accumulator in registers.
// Smem: K tile + V tile + transposed score tile = exactly 48 KB.
// ----------------------------------------------------------------------------
__global__ void __launch_bounds__(64) attn_kernel(const float* __restrict__ Q,
                                                  const float* __restrict__ K,
                                                  const float* __restrict__ V,
                                                  float* __restrict__ O) {
    __shared__ float Ks[64 * 64];
    __shared__ float Vs[64 * 64];
    __shared__ float scr[64 * 64];   // scr[k*64 + t]: bank = lane, conflict-free

    const int t  = threadIdx.x;       // query row within tile
    const int qt = blockIdx.x;        // q tile index
    const int h  = blockIdx.y;
    const int b  = blockIdx.z;
    const int q0 = qt * 64;

    const float* qptr = Q + ((size_t)(b * SEQ + q0 + t)) * DMODEL + h * DK;
    float q[DK];
#pragma unroll
    for (int d = 0; d < DK; d += 4) {
        float4 v4 = *(const float4*)(qptr + d);
        q[d] = v4.x; q[d + 1] = v4.y; q[d + 2] = v4.z; q[d + 3] = v4.w;
    }
    float o[DK];
#pragma unroll
    for (int d = 0; d < DK; d++) o[d] = 0.f;
    float m = -1e30f, l = 0.f;

    for (int kt = 0; kt <= qt; kt++) {
        const float* kbase = K + ((size_t)(b * SEQ + kt * 64)) * DMODEL + h * DK;
        const float* vbase = V + ((size_t)(b * SEQ + kt * 64)) * DMODEL + h * DK;
        // cooperative coalesced tile load: 1024 float4s / 64 threads
#pragma unroll
        for (int it = 0; it < 16; it++) {
            int flat4 = it * 64 + t;
            int kr = flat4 >> 4;
            int d4 = (flat4 & 15) * 4;
            *(float4*)&Ks[kr * 64 + d4] = *(const float4*)(kbase + (size_t)kr * DMODEL + d4);
            *(float4*)&Vs[kr * 64 + d4] = *(const float4*)(vbase + (size_t)kr * DMODEL + d4);
        }
        __syncthreads();

        const int kmax = (kt == qt) ? (t + 1) : 64;   // causal

        float tm = -1e30f;
        for (int k = 0; k < kmax; k++) {
            float s = 0.f;
#pragma unroll
            for (int d = 0; d < DK; d += 4) {
                float4 kv = *(const float4*)&Ks[k * 64 + d];
                s += q[d] * kv.x + q[d + 1] * kv.y + q[d + 2] * kv.z + q[d + 3] * kv.w;
            }
            s *= 0.125f;   // 1/sqrt(64)
            scr[k * 64 + t] = s;
            tm = fmaxf(tm, s);
        }

        float mn   = fmaxf(m, tm);
        float corr = __expf(m - mn);
        float lsum = 0.f;
        for (int k = 0; k < kmax; k++) {
            float p = __expf(scr[k * 64 + t] - mn);
            scr[k * 64 + t] = p;
            lsum += p;
        }
        l = l * corr + lsum;
#pragma unroll
        for (int d = 0; d < DK; d++) o[d] *= corr;

        for (int k = 0; k < kmax; k++) {
            float p = scr[k * 64 + t];
#pragma unroll
            for (int d = 0; d < DK; d += 4) {
                float4 vv = *(const float4*)&Vs[k * 64 + d];
                o[d]     += p * vv.x;
                o[d + 1] += p * vv.y;
                o[d + 2] += p * vv.z;
                o[d + 3] += p * vv.w;
            }
        }
        m = mn;
        __syncthreads();
    }

    float inv = 1.f / l;
    float* optr = O + ((size_t)(b * SEQ + q0 + t)) * DMODEL + h * DK;
#pragma unroll
    for (int d = 0; d < DK; d += 4) {
        float4 v4 = make_float4(o[d] * inv, o[d + 1] * inv, o[d + 2] * inv, o[d + 3] * inv);
        *(float4*)(optr + d) = v4;
    }
}

// ----------------------------------------------------------------------------
// Launch
// ----------------------------------------------------------------------------
extern "C" void kernel_launch(void* const* d_in, const int* in_sizes, int n_in,
                              void* d_out, int out_size) {
    (void)in_sizes; (void)n_in; (void)out_size;
    const float* x  = (const float*)d_in[0];
    const int*   tp = (const int*)d_in[1];
    const float* Wq = (const float*)d_in[2];
    const float* Wk = (const float*)d_in[3];
    const float* Wv = (const float*)d_in[4];
    const float* Wo = (const float*)d_in[5];
    float* out = (float*)d_out;

    float *Qp, *Kp, *Vp, *Op;
    cudaGetSymbolAddress((void**)&Qp, g_Q);
    cudaGetSymbolAddress((void**)&Kp, g_K);
    cudaGetSymbolAddress((void**)&Vp, g_V);
    cudaGetSymbolAddress((void**)&Op, g_O);

    dim3 gg(DMODEL / 64, MROWS / 64);   // (16, 64)
    gemm_nt<<<gg, 256>>>(x, Wq, Qp, MROWS, DMODEL, DMODEL);
    gemm_nt<<<gg, 256>>>(x, Wk, Kp, MROWS, DMODEL, DMODEL);
    gemm_nt<<<gg, 256>>>(x, Wv, Vp, MROWS, DMODEL, DMODEL);

    int ropeN = BATCH * SEQ * (DMODEL / 2);
    rope_kernel<<<(ropeN + 255) / 256, 256>>>(Qp, Kp, tp);

    attn_kernel<<<dim3(SEQ / 64, NHEADS, BATCH), 64>>>(Qp, Kp, Vp, Op);

    gemm_nt<<<gg, 256>>>(Op, Wo, out, MROWS, DMODEL, DMODEL);
}

// round 10
// speedup vs baseline: 1.2831x; 1.2831x over previous
#include <cuda_runtime.h>
#include <cuda_bf16.h>
#include <math.h>

// Problem constants
#define BATCH 2
#define SEQ 2048
#define DMODEL 1024
#define NHEADS 16
#define DK 64
#define MROWS (BATCH * SEQ)   // 4096

// Scratch buffers (device globals: no allocation allowed in kernel_launch)
__device__ float g_Q[MROWS * DMODEL];
__device__ float g_K[MROWS * DMODEL];
__device__ float g_V[MROWS * DMODEL];
__device__ float g_O[MROWS * DMODEL];
__device__ float2 g_rope[SEQ * 32];   // (cos, sin) per (s, pair-index)

// ----------------------------------------------------------------------------
// GEMM (NT): C[m,n] = sum_k A[m,k] * W[n,k]   (A: MxK, W: NxK, both K-contig)
// Tile 128x128, BK=16, 256 threads, 8x8 micro-tile (4+64 column split for
// conflict-free LDS.128), register prefetch of next k-tile during compute.
// ----------------------------------------------------------------------------
#define BM 128
#define BN 128
#define BKK 16
#define SPAD 132   // float4-aligned pad; STS 2-way conflict only (cheap)

__global__ void __launch_bounds__(256, 2) gemm_nt(const float* __restrict__ A,
                                                  const float* __restrict__ Wm,
                                                  float* __restrict__ C,
                                                  int M, int N, int K) {
    __shared__ float As[BKK][SPAD];
    __shared__ float Ws[BKK][SPAD];

    const int tid = threadIdx.x;
    const int tx = tid & 15;       // 0..15 -> N direction
    const int ty = tid >> 4;       // 0..15 -> M direction
    const int m0 = blockIdx.y * BM;
    const int n0 = blockIdx.x * BN;

    // cooperative load mapping: 256 threads x 2 rows each cover 128 rows x 16 k
    const int lr = tid >> 2;           // 0..63
    const int lc = (tid & 3) * 4;      // 0,4,8,12

    const float* aL0 = A  + (size_t)(m0 + lr)      * K + lc;
    const float* aL1 = A  + (size_t)(m0 + lr + 64) * K + lc;
    const float* wL0 = Wm + (size_t)(n0 + lr)      * K + lc;
    const float* wL1 = Wm + (size_t)(n0 + lr + 64) * K + lc;

    float acc[8][8];
#pragma unroll
    for (int i = 0; i < 8; i++)
#pragma unroll
        for (int j = 0; j < 8; j++) acc[i][j] = 0.f;

    // prologue: fetch first k-tile into registers
    float4 a0 = *(const float4*)(aL0);
    float4 a1 = *(const float4*)(aL1);
    float4 w0 = *(const float4*)(wL0);
    float4 w1 = *(const float4*)(wL1);

    for (int k0 = 0; k0 < K; k0 += BKK) {
        // stage registers -> smem (k-major, transposed)
        As[lc + 0][lr] = a0.x; As[lc + 1][lr] = a0.y;
        As[lc + 2][lr] = a0.z; As[lc + 3][lr] = a0.w;
        As[lc + 0][lr + 64] = a1.x; As[lc + 1][lr + 64] = a1.y;
        As[lc + 2][lr + 64] = a1.z; As[lc + 3][lr + 64] = a1.w;
        Ws[lc + 0][lr] = w0.x; Ws[lc + 1][lr] = w0.y;
        Ws[lc + 2][lr] = w0.z; Ws[lc + 3][lr] = w0.w;
        Ws[lc + 0][lr + 64] = w1.x; Ws[lc + 1][lr + 64] = w1.y;
        Ws[lc + 2][lr + 64] = w1.z; Ws[lc + 3][lr + 64] = w1.w;
        __syncthreads();

        // prefetch next k-tile (global latency hidden behind 1024 FFMAs)
        int kn = k0 + BKK;
        if (kn < K) {
            a0 = *(const float4*)(aL0 + kn);
            a1 = *(const float4*)(aL1 + kn);
            w0 = *(const float4*)(wL0 + kn);
            w1 = *(const float4*)(wL1 + kn);
        }

#pragma unroll
        for (int kk = 0; kk < BKK; kk++) {
            float4 av0 = *(const float4*)&As[kk][ty * 4];
            float4 av1 = *(const float4*)&As[kk][ty * 4 + 64];
            float4 wv0 = *(const float4*)&Ws[kk][tx * 4];
            float4 wv1 = *(const float4*)&Ws[kk][tx * 4 + 64];
            float ar[8] = {av0.x, av0.y, av0.z, av0.w, av1.x, av1.y, av1.z, av1.w};
            float br[8] = {wv0.x, wv0.y, wv0.z, wv0.w, wv1.x, wv1.y, wv1.z, wv1.w};
#pragma unroll
            for (int i = 0; i < 8; i++)
#pragma unroll
                for (int j = 0; j < 8; j++)
                    acc[i][j] += ar[i] * br[j];
        }
        __syncthreads();
    }

#pragma unroll
    for (int i = 0; i < 8; i++) {
        int mrow = m0 + ((i < 4) ? (ty * 4 + i) : (64 + ty * 4 + i - 4));
        float4 o0 = make_float4(acc[i][0], acc[i][1], acc[i][2], acc[i][3]);
        float4 o1 = make_float4(acc[i][4], acc[i][5], acc[i][6], acc[i][7]);
        *(float4*)&C[(size_t)mrow * N + n0 + tx * 4]      = o0;
        *(float4*)&C[(size_t)mrow * N + n0 + 64 + tx * 4] = o1;
    }
}

// ----------------------------------------------------------------------------
// RoPE stage 1: build (cos, sin) table once per launch with the same double
// math as before (identical values -> identical accuracy), 65536 threads only.
// ----------------------------------------------------------------------------
__global__ void rope_tables(const int* __restrict__ tp) {
    int idx = blockIdx.x * blockDim.x + threadIdx.x;   // over SEQ*32
    if (idx >= SEQ * 32) return;
    int s = idx >> 5;
    int i = idx & 31;
    double pos  = (double)tp[s];
    // theta^(-(2i)/64) = exp(-(2i/64) * ln(10000))
    double freq = exp(-((double)(2 * i) / 64.0) * 9.210340371976184);
    double ang  = pos * freq;
    g_rope[idx] = make_float2((float)cos(ang), (float)sin(ang));
}

// ----------------------------------------------------------------------------
// RoPE stage 2: pure fp32 apply, float2-coalesced, memory-bound (~15us).
// ----------------------------------------------------------------------------
__global__ void rope_apply(float2* __restrict__ Qb, float2* __restrict__ Kb) {
    int idx = blockIdx.x * blockDim.x + threadIdx.x;   // over B*S*(D/2)
    if (idx >= BATCH * SEQ * (DMODEL / 2)) return;
    int d2 = idx & (DMODEL / 2 - 1);   // 0..511
    int bs = idx >> 9;                 // 0..4095
    int s  = bs & (SEQ - 1);
    int i  = d2 & 31;                  // pair index within head

    float2 cs = g_rope[(s << 5) | i];

    // float2 element index: bs*512 + h*32 + i == idx (same layout)
    float2 q = Qb[idx];
    Qb[idx] = make_float2(q.x * cs.x - q.y * cs.y, q.x * cs.y + q.y * cs.x);
    float2 k = Kb[idx];
    Kb[idx] = make_float2(k.x * cs.x - k.y * cs.y, k.x * cs.y + k.y * cs.x);
}

// ----------------------------------------------------------------------------
// Causal flash attention. One block = one (b, h, 64-row q tile).
// 64 threads: thread t owns query row t. Q row + O accumulator in registers.
// ----------------------------------------------------------------------------
__global__ void __launch_bounds__(64) attn_kernel(const float* __restrict__ Q,
                                                  const float* __restrict__ K,
                                                  const float* __restrict__ V,
                                                  float* __restrict__ O) {
    __shared__ float Ks[64 * 64];
    __shared__ float Vs[64 * 64];
    __shared__ float scr[64 * 64];   // scr[k*64 + t]: bank = lane, conflict-free

    const int t  = threadIdx.x;       // query row within tile
    const int qt = blockIdx.x;        // q tile index
    const int h  = blockIdx.y;
    const int b  = blockIdx.z;
    const int q0 = qt * 64;

    const float* qptr = Q + ((size_t)(b * SEQ + q0 + t)) * DMODEL + h * DK;
    float q[DK];
#pragma unroll
    for (int d = 0; d < DK; d += 4) {
        float4 v4 = *(const float4*)(qptr + d);
        q[d] = v4.x; q[d + 1] = v4.y; q[d + 2] = v4.z; q[d + 3] = v4.w;
    }
    float o[DK];
#pragma unroll
    for (int d = 0; d < DK; d++) o[d] = 0.f;
    float m = -1e30f, l = 0.f;

    for (int kt = 0; kt <= qt; kt++) {
        const float* kbase = K + ((size_t)(b * SEQ + kt * 64)) * DMODEL + h * DK;
        const float* vbase = V + ((size_t)(b * SEQ + kt * 64)) * DMODEL + h * DK;
#pragma unroll
        for (int it = 0; it < 16; it++) {
            int flat4 = it * 64 + t;
            int kr = flat4 >> 4;
            int d4 = (flat4 & 15) * 4;
            *(float4*)&Ks[kr * 64 + d4] = *(const float4*)(kbase + (size_t)kr * DMODEL + d4);
            *(float4*)&Vs[kr * 64 + d4] = *(const float4*)(vbase + (size_t)kr * DMODEL + d4);
        }
        __syncthreads();

        const int kmax = (kt == qt) ? (t + 1) : 64;   // causal

        float tm = -1e30f;
        for (int k = 0; k < kmax; k++) {
            float s = 0.f;
#pragma unroll
            for (int d = 0; d < DK; d += 4) {
                float4 kv = *(const float4*)&Ks[k * 64 + d];
                s += q[d] * kv.x + q[d + 1] * kv.y + q[d + 2] * kv.z + q[d + 3] * kv.w;
            }
            s *= 0.125f;   // 1/sqrt(64)
            scr[k * 64 + t] = s;
            tm = fmaxf(tm, s);
        }

        float mn   = fmaxf(m, tm);
        float corr = __expf(m - mn);
        float lsum = 0.f;
        for (int k = 0; k < kmax; k++) {
            float p = __expf(scr[k * 64 + t] - mn);
            scr[k * 64 + t] = p;
            lsum += p;
        }
        l = l * corr + lsum;
#pragma unroll
        for (int d = 0; d < DK; d++) o[d] *= corr;

        for (int k = 0; k < kmax; k++) {
            float p = scr[k * 64 + t];
#pragma unroll
            for (int d = 0; d < DK; d += 4) {
                float4 vv = *(const float4*)&Vs[k * 64 + d];
                o[d]     += p * vv.x;
                o[d + 1] += p * vv.y;
                o[d + 2] += p * vv.z;
                o[d + 3] += p * vv.w;
            }
        }
        m = mn;
        __syncthreads();
    }

    float inv = 1.f / l;
    float* optr = O + ((size_t)(b * SEQ + q0 + t)) * DMODEL + h * DK;
#pragma unroll
    for (int d = 0; d < DK; d += 4) {
        float4 v4 = make_float4(o[d] * inv, o[d + 1] * inv, o[d + 2] * inv, o[d + 3] * inv);
        *(float4*)(optr + d) = v4;
    }
}

// ----------------------------------------------------------------------------
// Launch
// ----------------------------------------------------------------------------
extern "C" void kernel_launch(void* const* d_in, const int* in_sizes, int n_in,
                              void* d_out, int out_size) {
    (void)in_sizes; (void)n_in; (void)out_size;
    const float* x  = (const float*)d_in[0];
    const int*   tp = (const int*)d_in[1];
    const float* Wq = (const float*)d_in[2];
    const float* Wk = (const float*)d_in[3];
    const float* Wv = (const float*)d_in[4];
    const float* Wo = (const float*)d_in[5];
    float* out = (float*)d_out;

    float *Qp, *Kp, *Vp, *Op;
    cudaGetSymbolAddress((void**)&Qp, g_Q);
    cudaGetSymbolAddress((void**)&Kp, g_K);
    cudaGetSymbolAddress((void**)&Vp, g_V);
    cudaGetSymbolAddress((void**)&Op, g_O);

    dim3 gg(DMODEL / BN, MROWS / BM);   // (8, 32)
    gemm_nt<<<gg, 256>>>(x, Wq, Qp, MROWS, DMODEL, DMODEL);
    gemm_nt<<<gg, 256>>>(x, Wk, Kp, MROWS, DMODEL, DMODEL);
    gemm_nt<<<gg, 256>>>(x, Wv, Vp, MROWS, DMODEL, DMODEL);

    rope_tables<<<(SEQ * 32 + 255) / 256, 256>>>(tp);
    int ropeN = BATCH * SEQ * (DMODEL / 2);
    rope_apply<<<(ropeN + 255) / 256, 256>>>((float2*)Qp, (float2*)Kp);

    attn_kernel<<<dim3(SEQ / 64, NHEADS, BATCH), 64>>>(Qp, Kp, Vp, Op);

    gemm_nt<<<gg, 256>>>(Op, Wo, out, MROWS, DMODEL, DMODEL);
}

// round 11
// speedup vs baseline: 1.5395x; 1.1999x over previous
#include <cuda_runtime.h>
#include <cuda_bf16.h>
#include <math.h>

// Problem constants
#define BATCH 2
#define SEQ 2048
#define DMODEL 1024
#define NHEADS 16
#define DK 64
#define MROWS (BATCH * SEQ)   // 4096

// Scratch buffers (device globals: no allocation allowed in kernel_launch)
__device__ float g_Q[MROWS * DMODEL];
__device__ float g_K[MROWS * DMODEL];
__device__ float g_V[MROWS * DMODEL];
__device__ float g_O[MROWS * DMODEL];
__device__ float2 g_rope[SEQ * 32];   // (cos, sin) per (s, pair-index)

// ----------------------------------------------------------------------------
// tf32 helpers
// ----------------------------------------------------------------------------
__device__ __forceinline__ unsigned tf32r(float f) {
    unsigned u;
    asm("cvt.rna.tf32.f32 %0, %1;" : "=r"(u) : "f"(f));
    return u;
}

__device__ __forceinline__ void mma_tf32(float& c0, float& c1, float& c2, float& c3,
                                         unsigned a0, unsigned a1, unsigned a2, unsigned a3,
                                         unsigned b0, unsigned b1) {
    asm volatile(
        "mma.sync.aligned.m16n8k8.row.col.f32.tf32.tf32.f32 "
        "{%0,%1,%2,%3}, {%4,%5,%6,%7}, {%8,%9}, {%0,%1,%2,%3};"
        : "+f"(c0), "+f"(c1), "+f"(c2), "+f"(c3)
        : "r"(a0), "r"(a1), "r"(a2), "r"(a3), "r"(b0), "r"(b1));
}

// ----------------------------------------------------------------------------
// GEMM (NT) via tf32 tensor-core mma: C[m,n] = sum_k A[m,k] * W[n,k]
// Tile 128x128, BK=16, 256 threads = 8 warps, warp tile 64x32 (2x4 warp grid).
// Operands tf32-rounded once at smem staging. Smem stride 20 words:
// fragment LDS pattern (20*g + t) mod 32 is a 32-permutation -> conflict-free.
// ----------------------------------------------------------------------------
#define BM 128
#define BN 128
#define GBK 16
#define SSTR 20   // smem row stride in words

__global__ void __launch_bounds__(256, 2) gemm_nt(const float* __restrict__ A,
                                                  const float* __restrict__ Wm,
                                                  float* __restrict__ C,
                                                  int M, int N, int K) {
    __shared__ unsigned As[BM * SSTR];   // [m-row][k] tf32 bits
    __shared__ unsigned Bs[BN * SSTR];   // [n-row][k] tf32 bits

    const int tid  = threadIdx.x;
    const int lane = tid & 31;
    const int wid  = tid >> 5;
    const int wm   = wid & 1;        // 0..1 -> 64-row m slab
    const int wn   = wid >> 1;       // 0..3 -> 32-col n slab
    const int g    = lane >> 2;      // fragment group 0..7
    const int t4   = lane & 3;       // fragment thread-in-group 0..3

    const int m0 = blockIdx.y * BM;
    const int n0 = blockIdx.x * BN;

    // staging map: 512 float4 per matrix per tile, 2 per thread
    const int lrow = tid >> 2;       // 0..63
    const int lc4  = tid & 3;        // 0..3 (float4 col)

    const float* aP0 = A  + (size_t)(m0 + lrow)      * K + lc4 * 4;
    const float* aP1 = A  + (size_t)(m0 + lrow + 64) * K + lc4 * 4;
    const float* bP0 = Wm + (size_t)(n0 + lrow)      * K + lc4 * 4;
    const float* bP1 = Wm + (size_t)(n0 + lrow + 64) * K + lc4 * 4;

    float acc[4][4][4];
#pragma unroll
    for (int i = 0; i < 4; i++)
#pragma unroll
        for (int j = 0; j < 4; j++)
#pragma unroll
            for (int r = 0; r < 4; r++) acc[i][j][r] = 0.f;

    float4 pa0 = *(const float4*)(aP0);
    float4 pa1 = *(const float4*)(aP1);
    float4 pb0 = *(const float4*)(bP0);
    float4 pb1 = *(const float4*)(bP1);

    const unsigned* Abase = As + (64 * wm) * SSTR;
    const unsigned* Bbase = Bs + (32 * wn) * SSTR;

    for (int k0 = 0; k0 < K; k0 += GBK) {
        // stage (with tf32 rounding)
        {
            unsigned* d;
            d = &As[lrow * SSTR + lc4 * 4];
            d[0] = tf32r(pa0.x); d[1] = tf32r(pa0.y); d[2] = tf32r(pa0.z); d[3] = tf32r(pa0.w);
            d = &As[(lrow + 64) * SSTR + lc4 * 4];
            d[0] = tf32r(pa1.x); d[1] = tf32r(pa1.y); d[2] = tf32r(pa1.z); d[3] = tf32r(pa1.w);
            d = &Bs[lrow * SSTR + lc4 * 4];
            d[0] = tf32r(pb0.x); d[1] = tf32r(pb0.y); d[2] = tf32r(pb0.z); d[3] = tf32r(pb0.w);
            d = &Bs[(lrow + 64) * SSTR + lc4 * 4];
            d[0] = tf32r(pb1.x); d[1] = tf32r(pb1.y); d[2] = tf32r(pb1.z); d[3] = tf32r(pb1.w);
        }
        __syncthreads();

        // prefetch next k-slab (latency hidden behind 32 MMAs)
        int kn = k0 + GBK;
        if (kn < K) {
            pa0 = *(const float4*)(aP0 + kn);
            pa1 = *(const float4*)(aP1 + kn);
            pb0 = *(const float4*)(bP0 + kn);
            pb1 = *(const float4*)(bP1 + kn);
        }

#pragma unroll
        for (int kk = 0; kk < GBK; kk += 8) {
            unsigned bf[4][2];
#pragma unroll
            for (int jn = 0; jn < 4; jn++) {
                const unsigned* bp = Bbase + (8 * jn + g) * SSTR + kk + t4;
                bf[jn][0] = bp[0];
                bf[jn][1] = bp[4];
            }
#pragma unroll
            for (int im = 0; im < 4; im++) {
                const unsigned* ap0 = Abase + (16 * im + g) * SSTR + kk + t4;
                const unsigned* ap1 = ap0 + 8 * SSTR;
                unsigned a0 = ap0[0], a1 = ap1[0], a2 = ap0[4], a3 = ap1[4];
#pragma unroll
                for (int jn = 0; jn < 4; jn++)
                    mma_tf32(acc[im][jn][0], acc[im][jn][1], acc[im][jn][2], acc[im][jn][3],
                             a0, a1, a2, a3, bf[jn][0], bf[jn][1]);
            }
        }
        __syncthreads();
    }

    // epilogue: c0,c1 -> (row, 2t..2t+1), c2,c3 -> (row+8, ...)
#pragma unroll
    for (int im = 0; im < 4; im++) {
        int row = m0 + 64 * wm + 16 * im + g;
#pragma unroll
        for (int jn = 0; jn < 4; jn++) {
            int col = n0 + 32 * wn + 8 * jn + 2 * t4;
            *(float2*)&C[(size_t)row * N + col]       = make_float2(acc[im][jn][0], acc[im][jn][1]);
            *(float2*)&C[(size_t)(row + 8) * N + col] = make_float2(acc[im][jn][2], acc[im][jn][3]);
        }
    }
}

// ----------------------------------------------------------------------------
// RoPE stage 1: build (cos, sin) table with double math (65536 threads only).
// ----------------------------------------------------------------------------
__global__ void rope_tables(const int* __restrict__ tp) {
    int idx = blockIdx.x * blockDim.x + threadIdx.x;   // over SEQ*32
    if (idx >= SEQ * 32) return;
    int s = idx >> 5;
    int i = idx & 31;
    double pos  = (double)tp[s];
    double freq = exp(-((double)(2 * i) / 64.0) * 9.210340371976184);
    double ang  = pos * freq;
    g_rope[idx] = make_float2((float)cos(ang), (float)sin(ang));
}

// ----------------------------------------------------------------------------
// RoPE stage 2: pure fp32 apply, float2-coalesced, memory-bound.
// ----------------------------------------------------------------------------
__global__ void rope_apply(float2* __restrict__ Qb, float2* __restrict__ Kb) {
    int idx = blockIdx.x * blockDim.x + threadIdx.x;   // over B*S*(D/2)
    if (idx >= BATCH * SEQ * (DMODEL / 2)) return;
    int d2 = idx & (DMODEL / 2 - 1);
    int bs = idx >> 9;
    int s  = bs & (SEQ - 1);
    int i  = d2 & 31;

    float2 cs = g_rope[(s << 5) | i];

    float2 q = Qb[idx];
    Qb[idx] = make_float2(q.x * cs.x - q.y * cs.y, q.x * cs.y + q.y * cs.x);
    float2 k = Kb[idx];
    Kb[idx] = make_float2(k.x * cs.x - k.y * cs.y, k.x * cs.y + k.y * cs.x);
}

// ----------------------------------------------------------------------------
// Causal flash attention (fp32 SIMT). One block = one (b, h, 64-row q tile).
// qt reversed: longest blocks (most k-tiles) launch first -> smaller tail.
// ----------------------------------------------------------------------------
__global__ void __launch_bounds__(64) attn_kernel(const float* __restrict__ Q,
                                                  const float* __restrict__ K,
                                                  const float* __restrict__ V,
                                                  float* __restrict__ O) {
    __shared__ float Ks[64 * 64];
    __shared__ float Vs[64 * 64];
    __shared__ float scr[64 * 64];   // scr[k*64 + t]: bank = lane, conflict-free

    const int t  = threadIdx.x;
    const int qt = (int)gridDim.x - 1 - (int)blockIdx.x;   // longest first
    const int h  = blockIdx.y;
    const int b  = blockIdx.z;
    const int q0 = qt * 64;

    const float* qptr = Q + ((size_t)(b * SEQ + q0 + t)) * DMODEL + h * DK;
    float q[DK];
#pragma unroll
    for (int d = 0; d < DK; d += 4) {
        float4 v4 = *(const float4*)(qptr + d);
        q[d] = v4.x; q[d + 1] = v4.y; q[d + 2] = v4.z; q[d + 3] = v4.w;
    }
    float o[DK];
#pragma unroll
    for (int d = 0; d < DK; d++) o[d] = 0.f;
    float m = -1e30f, l = 0.f;

    for (int kt = 0; kt <= qt; kt++) {
        const float* kbase = K + ((size_t)(b * SEQ + kt * 64)) * DMODEL + h * DK;
        const float* vbase = V + ((size_t)(b * SEQ + kt * 64)) * DMODEL + h * DK;
#pragma unroll
        for (int it = 0; it < 16; it++) {
            int flat4 = it * 64 + t;
            int kr = flat4 >> 4;
            int d4 = (flat4 & 15) * 4;
            *(float4*)&Ks[kr * 64 + d4] = *(const float4*)(kbase + (size_t)kr * DMODEL + d4);
            *(float4*)&Vs[kr * 64 + d4] = *(const float4*)(vbase + (size_t)kr * DMODEL + d4);
        }
        __syncthreads();

        const int kmax = (kt == qt) ? (t + 1) : 64;   // causal

        float tm = -1e30f;
        for (int k = 0; k < kmax; k++) {
            float s = 0.f;
#pragma unroll
            for (int d = 0; d < DK; d += 4) {
                float4 kv = *(const float4*)&Ks[k * 64 + d];
                s += q[d] * kv.x + q[d + 1] * kv.y + q[d + 2] * kv.z + q[d + 3] * kv.w;
            }
            s *= 0.125f;   // 1/sqrt(64)
            scr[k * 64 + t] = s;
            tm = fmaxf(tm, s);
        }

        float mn   = fmaxf(m, tm);
        float corr = __expf(m - mn);
        float lsum = 0.f;
        for (int k = 0; k < kmax; k++) {
            float p = __expf(scr[k * 64 + t] - mn);
            scr[k * 64 + t] = p;
            lsum += p;
        }
        l = l * corr + lsum;
#pragma unroll
        for (int d = 0; d < DK; d++) o[d] *= corr;

        for (int k = 0; k < kmax; k++) {
            float p = scr[k * 64 + t];
#pragma unroll
            for (int d = 0; d < DK; d += 4) {
                float4 vv = *(const float4*)&Vs[k * 64 + d];
                o[d]     += p * vv.x;
                o[d + 1] += p * vv.y;
                o[d + 2] += p * vv.z;
                o[d + 3] += p * vv.w;
            }
        }
        m = mn;
        __syncthreads();
    }

    float inv = 1.f / l;
    float* optr = O + ((size_t)(b * SEQ + q0 + t)) * DMODEL + h * DK;
#pragma unroll
    for (int d = 0; d < DK; d += 4) {
        float4 v4 = make_float4(o[d] * inv, o[d + 1] * inv, o[d + 2] * inv, o[d + 3] * inv);
        *(float4*)(optr + d) = v4;
    }
}

// ----------------------------------------------------------------------------
// Launch
// ----------------------------------------------------------------------------
extern "C" void kernel_launch(void* const* d_in, const int* in_sizes, int n_in,
                              void* d_out, int out_size) {
    (void)in_sizes; (void)n_in; (void)out_size;
    const float* x  = (const float*)d_in[0];
    const int*   tp = (const int*)d_in[1];
    const float* Wq = (const float*)d_in[2];
    const float* Wk = (const float*)d_in[3];
    const float* Wv = (const float*)d_in[4];
    const float* Wo = (const float*)d_in[5];
    float* out = (float*)d_out;

    float *Qp, *Kp, *Vp, *Op;
    cudaGetSymbolAddress((void**)&Qp, g_Q);
    cudaGetSymbolAddress((void**)&Kp, g_K);
    cudaGetSymbolAddress((void**)&Vp, g_V);
    cudaGetSymbolAddress((void**)&Op, g_O);

    dim3 gg(DMODEL / BN, MROWS / BM);   // (8, 32)
    gemm_nt<<<gg, 256>>>(x, Wq, Qp, MROWS, DMODEL, DMODEL);
    gemm_nt<<<gg, 256>>>(x, Wk, Kp, MROWS, DMODEL, DMODEL);
    gemm_nt<<<gg, 256>>>(x, Wv, Vp, MROWS, DMODEL, DMODEL);

    rope_tables<<<(SEQ * 32 + 255) / 256, 256>>>(tp);
    int ropeN = BATCH * SEQ * (DMODEL / 2);
    rope_apply<<<(ropeN + 255) / 256, 256>>>((float2*)Qp, (float2*)Kp);

    attn_kernel<<<dim3(SEQ / 64, NHEADS, BATCH), 64>>>(Qp, Kp, Vp, Op);

    gemm_nt<<<gg, 256>>>(Op, Wo, out, MROWS, DMODEL, DMODEL);
}

// round 12
// speedup vs baseline: 1.6052x; 1.0426x over previous
#include <cuda_runtime.h>
#include <cuda_bf16.h>
#include <math.h>

// Problem constants
#define BATCH 2
#define SEQ 2048
#define DMODEL 1024
#define NHEADS 16
#define DK 64
#define MROWS (BATCH * SEQ)   // 4096

// Scratch buffers (device globals: no allocation allowed in kernel_launch)
__device__ float g_Q[MROWS * DMODEL];
__device__ float g_K[MROWS * DMODEL];
__device__ float g_V[MROWS * DMODEL];
__device__ float g_O[MROWS * DMODEL];
__device__ float2 g_rope[SEQ * 32];   // (cos, sin) per (s, pair-index)

// ----------------------------------------------------------------------------
// tf32 helpers
// ----------------------------------------------------------------------------
__device__ __forceinline__ unsigned tf32r(float f) {
    unsigned u;
    asm("cvt.rna.tf32.f32 %0, %1;" : "=r"(u) : "f"(f));
    return u;
}

__device__ __forceinline__ void mma_tf32(float& c0, float& c1, float& c2, float& c3,
                                         unsigned a0, unsigned a1, unsigned a2, unsigned a3,
                                         unsigned b0, unsigned b1) {
    asm volatile(
        "mma.sync.aligned.m16n8k8.row.col.f32.tf32.tf32.f32 "
        "{%0,%1,%2,%3}, {%4,%5,%6,%7}, {%8,%9}, {%0,%1,%2,%3};"
        : "+f"(c0), "+f"(c1), "+f"(c2), "+f"(c3)
        : "r"(a0), "r"(a1), "r"(a2), "r"(a3), "r"(b0), "r"(b1));
}

// ----------------------------------------------------------------------------
// GEMM (NT) via tf32 tensor-core mma: C[m,n] = sum_k A[m,k] * W[n,k]
// Tile 128x128, BK=16, 256 threads = 8 warps, warp tile 64x32 (2x4 warp grid).
// Operands tf32-rounded once at smem staging. Smem stride 20 words:
// fragment LDS pattern (20*g + t) mod 32 is a 32-permutation -> conflict-free.
// ----------------------------------------------------------------------------
#define BM 128
#define BN 128
#define GBK 16
#define SSTR 20   // smem row stride in words

__global__ void __launch_bounds__(256, 2) gemm_nt(const float* __restrict__ A,
                                                  const float* __restrict__ Wm,
                                                  float* __restrict__ C,
                                                  int M, int N, int K) {
    __shared__ unsigned As[BM * SSTR];   // [m-row][k] tf32 bits
    __shared__ unsigned Bs[BN * SSTR];   // [n-row][k] tf32 bits

    const int tid  = threadIdx.x;
    const int lane = tid & 31;
    const int wid  = tid >> 5;
    const int wm   = wid & 1;        // 0..1 -> 64-row m slab
    const int wn   = wid >> 1;       // 0..3 -> 32-col n slab
    const int g    = lane >> 2;      // fragment group 0..7
    const int t4   = lane & 3;       // fragment thread-in-group 0..3

    const int m0 = blockIdx.y * BM;
    const int n0 = blockIdx.x * BN;

    // staging map: 512 float4 per matrix per tile, 2 per thread
    const int lrow = tid >> 2;       // 0..63
    const int lc4  = tid & 3;        // 0..3 (float4 col)

    const float* aP0 = A  + (size_t)(m0 + lrow)      * K + lc4 * 4;
    const float* aP1 = A  + (size_t)(m0 + lrow + 64) * K + lc4 * 4;
    const float* bP0 = Wm + (size_t)(n0 + lrow)      * K + lc4 * 4;
    const float* bP1 = Wm + (size_t)(n0 + lrow + 64) * K + lc4 * 4;

    float acc[4][4][4];
#pragma unroll
    for (int i = 0; i < 4; i++)
#pragma unroll
        for (int j = 0; j < 4; j++)
#pragma unroll
            for (int r = 0; r < 4; r++) acc[i][j][r] = 0.f;

    float4 pa0 = *(const float4*)(aP0);
    float4 pa1 = *(const float4*)(aP1);
    float4 pb0 = *(const float4*)(bP0);
    float4 pb1 = *(const float4*)(bP1);

    const unsigned* Abase = As + (64 * wm) * SSTR;
    const unsigned* Bbase = Bs + (32 * wn) * SSTR;

    for (int k0 = 0; k0 < K; k0 += GBK) {
        // stage (with tf32 rounding)
        {
            unsigned* d;
            d = &As[lrow * SSTR + lc4 * 4];
            d[0] = tf32r(pa0.x); d[1] = tf32r(pa0.y); d[2] = tf32r(pa0.z); d[3] = tf32r(pa0.w);
            d = &As[(lrow + 64) * SSTR + lc4 * 4];
            d[0] = tf32r(pa1.x); d[1] = tf32r(pa1.y); d[2] = tf32r(pa1.z); d[3] = tf32r(pa1.w);
            d = &Bs[lrow * SSTR + lc4 * 4];
            d[0] = tf32r(pb0.x); d[1] = tf32r(pb0.y); d[2] = tf32r(pb0.z); d[3] = tf32r(pb0.w);
            d = &Bs[(lrow + 64) * SSTR + lc4 * 4];
            d[0] = tf32r(pb1.x); d[1] = tf32r(pb1.y); d[2] = tf32r(pb1.z); d[3] = tf32r(pb1.w);
        }
        __syncthreads();

        // prefetch next k-slab (latency hidden behind 32 MMAs)
        int kn = k0 + GBK;
        if (kn < K) {
            pa0 = *(const float4*)(aP0 + kn);
            pa1 = *(const float4*)(aP1 + kn);
            pb0 = *(const float4*)(bP0 + kn);
            pb1 = *(const float4*)(bP1 + kn);
        }

#pragma unroll
        for (int kk = 0; kk < GBK; kk += 8) {
            unsigned bf[4][2];
#pragma unroll
            for (int jn = 0; jn < 4; jn++) {
                const unsigned* bp = Bbase + (8 * jn + g) * SSTR + kk + t4;
                bf[jn][0] = bp[0];
                bf[jn][1] = bp[4];
            }
#pragma unroll
            for (int im = 0; im < 4; im++) {
                const unsigned* ap0 = Abase + (16 * im + g) * SSTR + kk + t4;
                const unsigned* ap1 = ap0 + 8 * SSTR;
                unsigned a0 = ap0[0], a1 = ap1[0], a2 = ap0[4], a3 = ap1[4];
#pragma unroll
                for (int jn = 0; jn < 4; jn++)
                    mma_tf32(acc[im][jn][0], acc[im][jn][1], acc[im][jn][2], acc[im][jn][3],
                             a0, a1, a2, a3, bf[jn][0], bf[jn][1]);
            }
        }
        __syncthreads();
    }

    // epilogue: c0,c1 -> (row, 2t..2t+1), c2,c3 -> (row+8, ...)
#pragma unroll
    for (int im = 0; im < 4; im++) {
        int row = m0 + 64 * wm + 16 * im + g;
#pragma unroll
        for (int jn = 0; jn < 4; jn++) {
            int col = n0 + 32 * wn + 8 * jn + 2 * t4;
            *(float2*)&C[(size_t)row * N + col]       = make_float2(acc[im][jn][0], acc[im][jn][1]);
            *(float2*)&C[(size_t)(row + 8) * N + col] = make_float2(acc[im][jn][2], acc[im][jn][3]);
        }
    }
}

// ----------------------------------------------------------------------------
// RoPE stage 1: build (cos, sin) table with double math (65536 threads only).
// ----------------------------------------------------------------------------
__global__ void rope_tables(const int* __restrict__ tp) {
    int idx = blockIdx.x * blockDim.x + threadIdx.x;   // over SEQ*32
    if (idx >= SEQ * 32) return;
    int s = idx >> 5;
    int i = idx & 31;
    double pos  = (double)tp[s];
    double freq = exp(-((double)(2 * i) / 64.0) * 9.210340371976184);
    double ang  = pos * freq;
    g_rope[idx] = make_float2((float)cos(ang), (float)sin(ang));
}

// ----------------------------------------------------------------------------
// RoPE stage 2: pure fp32 apply, float2-coalesced, memory-bound.
// ----------------------------------------------------------------------------
__global__ void rope_apply(float2* __restrict__ Qb, float2* __restrict__ Kb) {
    int idx = blockIdx.x * blockDim.x + threadIdx.x;   // over B*S*(D/2)
    if (idx >= BATCH * SEQ * (DMODEL / 2)) return;
    int d2 = idx & (DMODEL / 2 - 1);
    int bs = idx >> 9;
    int s  = bs & (SEQ - 1);
    int i  = d2 & 31;

    float2 cs = g_rope[(s << 5) | i];

    float2 q = Qb[idx];
    Qb[idx] = make_float2(q.x * cs.x - q.y * cs.y, q.x * cs.y + q.y * cs.x);
    float2 k = Kb[idx];
    Kb[idx] = make_float2(k.x * cs.x - k.y * cs.y, k.x * cs.y + k.y * cs.x);
}

// ----------------------------------------------------------------------------
// Causal flash attention (fp32 SIMT). One block = one (b, h, 64-row q tile).
// qt reversed: longest blocks (most k-tiles) launch first -> smaller tail.
// ----------------------------------------------------------------------------
__global__ void __launch_bounds__(64) attn_kernel(const float* __restrict__ Q,
                                                  const float* __restrict__ K,
                                                  const float* __restrict__ V,
                                                  float* __restrict__ O) {
    __shared__ float Ks[64 * 64];
    __shared__ float Vs[64 * 64];
    __shared__ float scr[64 * 64];   // scr[k*64 + t]: bank = lane, conflict-free

    const int t  = threadIdx.x;
    const int qt = (int)gridDim.x - 1 - (int)blockIdx.x;   // longest first
    const int h  = blockIdx.y;
    const int b  = blockIdx.z;
    const int q0 = qt * 64;

    const float* qptr = Q + ((size_t)(b * SEQ + q0 + t)) * DMODEL + h * DK;
    float q[DK];
#pragma unroll
    for (int d = 0; d < DK; d += 4) {
        float4 v4 = *(const float4*)(qptr + d);
        q[d] = v4.x; q[d + 1] = v4.y; q[d + 2] = v4.z; q[d + 3] = v4.w;
    }
    float o[DK];
#pragma unroll
    for (int d = 0; d < DK; d++) o[d] = 0.f;
    float m = -1e30f, l = 0.f;

    for (int kt = 0; kt <= qt; kt++) {
        const float* kbase = K + ((size_t)(b * SEQ + kt * 64)) * DMODEL + h * DK;
        const float* vbase = V + ((size_t)(b * SEQ + kt * 64)) * DMODEL + h * DK;
#pragma unroll
        for (int it = 0; it < 16; it++) {
            int flat4 = it * 64 + t;
            int kr = flat4 >> 4;
            int d4 = (flat4 & 15) * 4;
            *(float4*)&Ks[kr * 64 + d4] = *(const float4*)(kbase + (size_t)kr * DMODEL + d4);
            *(float4*)&Vs[kr * 64 + d4] = *(const float4*)(vbase + (size_t)kr * DMODEL + d4);
        }
        __syncthreads();

        const int kmax = (kt == qt) ? (t + 1) : 64;   // causal

        float tm = -1e30f;
        for (int k = 0; k < kmax; k++) {
            float s = 0.f;
#pragma unroll
            for (int d = 0; d < DK; d += 4) {
                float4 kv = *(const float4*)&Ks[k * 64 + d];
                s += q[d] * kv.x + q[d + 1] * kv.y + q[d + 2] * kv.z + q[d + 3] * kv.w;
            }
            s *= 0.125f;   // 1/sqrt(64)
            scr[k * 64 + t] = s;
            tm = fmaxf(tm, s);
        }

        float mn   = fmaxf(m, tm);
        float corr = __expf(m - mn);
        float lsum = 0.f;
        for (int k = 0; k < kmax; k++) {
            float p = __expf(scr[k * 64 + t] - mn);
            scr[k * 64 + t] = p;
            lsum += p;
        }
        l = l * corr + lsum;
#pragma unroll
        for (int d = 0; d < DK; d++) o[d] *= corr;

        for (int k = 0; k < kmax; k++) {
            float p = scr[k * 64 + t];
#pragma unroll
            for (int d = 0; d < DK; d += 4) {
                float4 vv = *(const float4*)&Vs[k * 64 + d];
                o[d]     += p * vv.x;
                o[d + 1] += p * vv.y;
                o[d + 2] += p * vv.z;
                o[d + 3] += p * vv.w;
            }
        }
        m = mn;
        __syncthreads();
    }

    float inv = 1.f / l;
    float* optr = O + ((size_t)(b * SEQ + q0 + t)) * DMODEL + h * DK;
#pragma unroll
    for (int d = 0; d < DK; d += 4) {
        float4 v4 = make_float4(o[d] * inv, o[d + 1] * inv, o[d + 2] * inv, o[d + 3] * inv);
        *(float4*)(optr + d) = v4;
    }
}

// ----------------------------------------------------------------------------
// Launch
// ----------------------------------------------------------------------------
extern "C" void kernel_launch(void* const* d_in, const int* in_sizes, int n_in,
                              void* d_out, int out_size) {
    (void)in_sizes; (void)n_in; (void)out_size;
    const float* x  = (const float*)d_in[0];
    const int*   tp = (const int*)d_in[1];
    const float* Wq = (const float*)d_in[2];
    const float* Wk = (const float*)d_in[3];
    const float* Wv = (const float*)d_in[4];
    const float* Wo = (const float*)d_in[5];
    float* out = (float*)d_out;

    float *Qp, *Kp, *Vp, *Op;
    cudaGetSymbolAddress((void**)&Qp, g_Q);
    cudaGetSymbolAddress((void**)&Kp, g_K);
    cudaGetSymbolAddress((void**)&Vp, g_V);
    cudaGetSymbolAddress((void**)&Op, g_O);

    dim3 gg(DMODEL / BN, MROWS / BM);   // (8, 32)
    gemm_nt<<<gg, 256>>>(x, Wq, Qp, MROWS, DMODEL, DMODEL);
    gemm_nt<<<gg, 256>>>(x, Wk, Kp, MROWS, DMODEL, DMODEL);
    gemm_nt<<<gg, 256>>>(x, Wv, Vp, MROWS, DMODEL, DMODEL);

    rope_tables<<<(SEQ * 32 + 255) / 256, 256>>>(tp);
    int ropeN = BATCH * SEQ * (DMODEL / 2);
    rope_apply<<<(ropeN + 255) / 256, 256>>>((float2*)Qp, (float2*)Kp);

    attn_kernel<<<dim3(SEQ / 64, NHEADS, BATCH), 64>>>(Qp, Kp, Vp, Op);

    gemm_nt<<<gg, 256>>>(Op, Wo, out, MROWS, DMODEL, DMODEL);
}

// round 13
// speedup vs baseline: 1.6237x; 1.0115x over previous
#include <cuda_runtime.h>
#include <cuda_bf16.h>
#include <math.h>

// Problem constants
#define BATCH 2
#define SEQ 2048
#define DMODEL 1024
#define NHEADS 16
#define DK 64
#define MROWS (BATCH * SEQ)   // 4096

// Scratch buffers (device globals: no allocation allowed in kernel_launch)
__device__ float g_Q[MROWS * DMODEL];
__device__ float g_K[MROWS * DMODEL];
__device__ float g_V[MROWS * DMODEL];
__device__ float g_O[MROWS * DMODEL];
__device__ float2 g_rope[SEQ * 32];   // (cos, sin) per (s, pair-index)

// ----------------------------------------------------------------------------
// tf32 helpers
// ----------------------------------------------------------------------------
__device__ __forceinline__ unsigned tf32r(float f) {
    unsigned u;
    asm("cvt.rna.tf32.f32 %0, %1;" : "=r"(u) : "f"(f));
    return u;
}

__device__ __forceinline__ void mma_tf32(float& c0, float& c1, float& c2, float& c3,
                                         unsigned a0, unsigned a1, unsigned a2, unsigned a3,
                                         unsigned b0, unsigned b1) {
    asm volatile(
        "mma.sync.aligned.m16n8k8.row.col.f32.tf32.tf32.f32 "
        "{%0,%1,%2,%3}, {%4,%5,%6,%7}, {%8,%9}, {%0,%1,%2,%3};"
        : "+f"(c0), "+f"(c1), "+f"(c2), "+f"(c3)
        : "r"(a0), "r"(a1), "r"(a2), "r"(a3), "r"(b0), "r"(b1));
}

// ----------------------------------------------------------------------------
// GEMM (NT) via tf32 tensor-core mma: C[m,n] = sum_k A[m,k] * W[n,k]
// Tile 128x128, BK=16, 256 threads = 8 warps, warp tile 64x32 (2x4 warp grid).
// Operands tf32-rounded once at smem staging. Smem stride 20 words:
// fragment LDS pattern (20*g + t) mod 32 is a 32-permutation -> conflict-free.
// ----------------------------------------------------------------------------
#define BM 128
#define BN 128
#define GBK 16
#define SSTR 20   // smem row stride in words

__global__ void __launch_bounds__(256, 2) gemm_nt(const float* __restrict__ A,
                                                  const float* __restrict__ Wm,
                                                  float* __restrict__ C,
                                                  int M, int N, int K) {
    __shared__ unsigned As[BM * SSTR];   // [m-row][k] tf32 bits
    __shared__ unsigned Bs[BN * SSTR];   // [n-row][k] tf32 bits

    const int tid  = threadIdx.x;
    const int lane = tid & 31;
    const int wid  = tid >> 5;
    const int wm   = wid & 1;        // 0..1 -> 64-row m slab
    const int wn   = wid >> 1;       // 0..3 -> 32-col n slab
    const int g    = lane >> 2;      // fragment group 0..7
    const int t4   = lane & 3;       // fragment thread-in-group 0..3

    const int m0 = blockIdx.y * BM;
    const int n0 = blockIdx.x * BN;

    // staging map: 512 float4 per matrix per tile, 2 per thread
    const int lrow = tid >> 2;       // 0..63
    const int lc4  = tid & 3;        // 0..3 (float4 col)

    const float* aP0 = A  + (size_t)(m0 + lrow)      * K + lc4 * 4;
    const float* aP1 = A  + (size_t)(m0 + lrow + 64) * K + lc4 * 4;
    const float* bP0 = Wm + (size_t)(n0 + lrow)      * K + lc4 * 4;
    const float* bP1 = Wm + (size_t)(n0 + lrow + 64) * K + lc4 * 4;

    float acc[4][4][4];
#pragma unroll
    for (int i = 0; i < 4; i++)
#pragma unroll
        for (int j = 0; j < 4; j++)
#pragma unroll
            for (int r = 0; r < 4; r++) acc[i][j][r] = 0.f;

    float4 pa0 = *(const float4*)(aP0);
    float4 pa1 = *(const float4*)(aP1);
    float4 pb0 = *(const float4*)(bP0);
    float4 pb1 = *(const float4*)(bP1);

    const unsigned* Abase = As + (64 * wm) * SSTR;
    const unsigned* Bbase = Bs + (32 * wn) * SSTR;

    for (int k0 = 0; k0 < K; k0 += GBK) {
        // stage (with tf32 rounding)
        {
            unsigned* d;
            d = &As[lrow * SSTR + lc4 * 4];
            d[0] = tf32r(pa0.x); d[1] = tf32r(pa0.y); d[2] = tf32r(pa0.z); d[3] = tf32r(pa0.w);
            d = &As[(lrow + 64) * SSTR + lc4 * 4];
            d[0] = tf32r(pa1.x); d[1] = tf32r(pa1.y); d[2] = tf32r(pa1.z); d[3] = tf32r(pa1.w);
            d = &Bs[lrow * SSTR + lc4 * 4];
            d[0] = tf32r(pb0.x); d[1] = tf32r(pb0.y); d[2] = tf32r(pb0.z); d[3] = tf32r(pb0.w);
            d = &Bs[(lrow + 64) * SSTR + lc4 * 4];
            d[0] = tf32r(pb1.x); d[1] = tf32r(pb1.y); d[2] = tf32r(pb1.z); d[3] = tf32r(pb1.w);
        }
        __syncthreads();

        // prefetch next k-slab (latency hidden behind 32 MMAs)
        int kn = k0 + GBK;
        if (kn < K) {
            pa0 = *(const float4*)(aP0 + kn);
            pa1 = *(const float4*)(aP1 + kn);
            pb0 = *(const float4*)(bP0 + kn);
            pb1 = *(const float4*)(bP1 + kn);
        }

#pragma unroll
        for (int kk = 0; kk < GBK; kk += 8) {
            unsigned bf[4][2];
#pragma unroll
            for (int jn = 0; jn < 4; jn++) {
                const unsigned* bp = Bbase + (8 * jn + g) * SSTR + kk + t4;
                bf[jn][0] = bp[0];
                bf[jn][1] = bp[4];
            }
#pragma unroll
            for (int im = 0; im < 4; im++) {
                const unsigned* ap0 = Abase + (16 * im + g) * SSTR + kk + t4;
                const unsigned* ap1 = ap0 + 8 * SSTR;
                unsigned a0 = ap0[0], a1 = ap1[0], a2 = ap0[4], a3 = ap1[4];
#pragma unroll
                for (int jn = 0; jn < 4; jn++)
                    mma_tf32(acc[im][jn][0], acc[im][jn][1], acc[im][jn][2], acc[im][jn][3],
                             a0, a1, a2, a3, bf[jn][0], bf[jn][1]);
            }
        }
        __syncthreads();
    }

    // epilogue: c0,c1 -> (row, 2t..2t+1), c2,c3 -> (row+8, ...)
#pragma unroll
    for (int im = 0; im < 4; im++) {
        int row = m0 + 64 * wm + 16 * im + g;
#pragma unroll
        for (int jn = 0; jn < 4; jn++) {
            int col = n0 + 32 * wn + 8 * jn + 2 * t4;
            *(float2*)&C[(size_t)row * N + col]       = make_float2(acc[im][jn][0], acc[im][jn][1]);
            *(float2*)&C[(size_t)(row + 8) * N + col] = make_float2(acc[im][jn][2], acc[im][jn][3]);
        }
    }
}

// ----------------------------------------------------------------------------
// RoPE stage 1: build (cos, sin) table with double math (65536 threads only).
// ----------------------------------------------------------------------------
__global__ void rope_tables(const int* __restrict__ tp) {
    int idx = blockIdx.x * blockDim.x + threadIdx.x;   // over SEQ*32
    if (idx >= SEQ * 32) return;
    int s = idx >> 5;
    int i = idx & 31;
    double pos  = (double)tp[s];
    double freq = exp(-((double)(2 * i) / 64.0) * 9.210340371976184);
    double ang  = pos * freq;
    g_rope[idx] = make_float2((float)cos(ang), (float)sin(ang));
}

// ----------------------------------------------------------------------------
// RoPE stage 2: pure fp32 apply, float2-coalesced, memory-bound.
// ----------------------------------------------------------------------------
__global__ void rope_apply(float2* __restrict__ Qb, float2* __restrict__ Kb) {
    int idx = blockIdx.x * blockDim.x + threadIdx.x;   // over B*S*(D/2)
    if (idx >= BATCH * SEQ * (DMODEL / 2)) return;
    int d2 = idx & (DMODEL / 2 - 1);
    int bs = idx >> 9;
    int s  = bs & (SEQ - 1);
    int i  = d2 & 31;

    float2 cs = g_rope[(s << 5) | i];

    float2 q = Qb[idx];
    Qb[idx] = make_float2(q.x * cs.x - q.y * cs.y, q.x * cs.y + q.y * cs.x);
    float2 k = Kb[idx];
    Kb[idx] = make_float2(k.x * cs.x - k.y * cs.y, k.x * cs.y + k.y * cs.x);
}

// ----------------------------------------------------------------------------
// Causal flash attention (fp32 SIMT). One block = one (b, h, 64-row q tile).
// qt reversed: longest blocks (most k-tiles) launch first -> smaller tail.
// ----------------------------------------------------------------------------
__global__ void __launch_bounds__(64) attn_kernel(const float* __restrict__ Q,
                                                  const float* __restrict__ K,
                                                  const float* __restrict__ V,
                                                  float* __restrict__ O) {
    __shared__ float Ks[64 * 64];
    __shared__ float Vs[64 * 64];
    __shared__ float scr[64 * 64];   // scr[k*64 + t]: bank = lane, conflict-free

    const int t  = threadIdx.x;
    const int qt = (int)gridDim.x - 1 - (int)blockIdx.x;   // longest first
    const int h  = blockIdx.y;
    const int b  = blockIdx.z;
    const int q0 = qt * 64;

    const float* qptr = Q + ((size_t)(b * SEQ + q0 + t)) * DMODEL + h * DK;
    float q[DK];
#pragma unroll
    for (int d = 0; d < DK; d += 4) {
        float4 v4 = *(const float4*)(qptr + d);
        q[d] = v4.x; q[d + 1] = v4.y; q[d + 2] = v4.z; q[d + 3] = v4.w;
    }
    float o[DK];
#pragma unroll
    for (int d = 0; d < DK; d++) o[d] = 0.f;
    float m = -1e30f, l = 0.f;

    for (int kt = 0; kt <= qt; kt++) {
        const float* kbase = K + ((size_t)(b * SEQ + kt * 64)) * DMODEL + h * DK;
        const float* vbase = V + ((size_t)(b * SEQ + kt * 64)) * DMODEL + h * DK;
#pragma unroll
        for (int it = 0; it < 16; it++) {
            int flat4 = it * 64 + t;
            int kr = flat4 >> 4;
            int d4 = (flat4 & 15) * 4;
            *(float4*)&Ks[kr * 64 + d4] = *(const float4*)(kbase + (size_t)kr * DMODEL + d4);
            *(float4*)&Vs[kr * 64 + d4] = *(const float4*)(vbase + (size_t)kr * DMODEL + d4);
        }
        __syncthreads();

        const int kmax = (kt == qt) ? (t + 1) : 64;   // causal

        float tm = -1e30f;
        for (int k = 0; k < kmax; k++) {
            float s = 0.f;
#pragma unroll
            for (int d = 0; d < DK; d += 4) {
                float4 kv = *(const float4*)&Ks[k * 64 + d];
                s += q[d] * kv.x + q[d + 1] * kv.y + q[d + 2] * kv.z + q[d + 3] * kv.w;
            }
            s *= 0.125f;   // 1/sqrt(64)
            scr[k * 64 + t] = s;
            tm = fmaxf(tm, s);
        }

        float mn   = fmaxf(m, tm);
        float corr = __expf(m - mn);
        float lsum = 0.f;
        for (int k = 0; k < kmax; k++) {
            float p = __expf(scr[k * 64 + t] - mn);
            scr[k * 64 + t] = p;
            lsum += p;
        }
        l = l * corr + lsum;
#pragma unroll
        for (int d = 0; d < DK; d++) o[d] *= corr;

        for (int k = 0; k < kmax; k++) {
            float p = scr[k * 64 + t];
#pragma unroll
            for (int d = 0; d < DK; d += 4) {
                float4 vv = *(const float4*)&Vs[k * 64 + d];
                o[d]     += p * vv.x;
                o[d + 1] += p * vv.y;
                o[d + 2] += p * vv.z;
                o[d + 3] += p * vv.w;
            }
        }
        m = mn;
        __syncthreads();
    }

    float inv = 1.f / l;
    float* optr = O + ((size_t)(b * SEQ + q0 + t)) * DMODEL + h * DK;
#pragma unroll
    for (int d = 0; d < DK; d += 4) {
        float4 v4 = make_float4(o[d] * inv, o[d + 1] * inv, o[d + 2] * inv, o[d + 3] * inv);
        *(float4*)(optr + d) = v4;
    }
}

// ----------------------------------------------------------------------------
// Launch
// ----------------------------------------------------------------------------
extern "C" void kernel_launch(void* const* d_in, const int* in_sizes, int n_in,
                              void* d_out, int out_size) {
    (void)in_sizes; (void)n_in; (void)out_size;
    const float* x  = (const float*)d_in[0];
    const int*   tp = (const int*)d_in[1];
    const float* Wq = (const float*)d_in[2];
    const float* Wk = (const float*)d_in[3];
    const float* Wv = (const float*)d_in[4];
    const float* Wo = (const float*)d_in[5];
    float* out = (float*)d_out;

    float *Qp, *Kp, *Vp, *Op;
    cudaGetSymbolAddress((void**)&Qp, g_Q);
    cudaGetSymbolAddress((void**)&Kp, g_K);
    cudaGetSymbolAddress((void**)&Vp, g_V);
    cudaGetSymbolAddress((void**)&Op, g_O);

    dim3 gg(DMODEL / BN, MROWS / BM);   // (8, 32)
    gemm_nt<<<gg, 256>>>(x, Wq, Qp, MROWS, DMODEL, DMODEL);
    gemm_nt<<<gg, 256>>>(x, Wk, Kp, MROWS, DMODEL, DMODEL);
    gemm_nt<<<gg, 256>>>(x, Wv, Vp, MROWS, DMODEL, DMODEL);

    rope_tables<<<(SEQ * 32 + 255) / 256, 256>>>(tp);
    int ropeN = BATCH * SEQ * (DMODEL / 2);
    rope_apply<<<(ropeN + 255) / 256, 256>>>((float2*)Qp, (float2*)Kp);

    attn_kernel<<<dim3(SEQ / 64, NHEADS, BATCH), 64>>>(Qp, Kp, Vp, Op);

    gemm_nt<<<gg, 256>>>(Op, Wo, out, MROWS, DMODEL, DMODEL);
}